// round 11
// baseline (speedup 1.0000x reference)
#include <cuda_runtime.h>
#include <cuda_bf16.h>
#include <cstdint>

#define N_NODES 50000
#define N_EDGES 800000
#define DIM 128

// ---------------- device scratch (no allocations allowed) ----------------
__device__ int   g_count[N_NODES];
__device__ int   g_rowptr[N_NODES + 1];
__device__ int   g_esrc[N_EDGES];
__device__ int   g_bsum[256];
__device__ int   g_boff[256];
__device__ float g_agg[N_NODES * DIM];
__device__ float g_h1[N_NODES * DIM];
__device__ float g_h2[N_NODES * DIM];
__device__ float g_s[N_NODES * DIM];   // self-GEMM partial sums
__device__ float g_wt0[256 * 128];     // tf32-rounded [Wself0;Wneigh0]
__device__ float g_wt1[256 * 128];
__device__ float g_wt2[256 * 64];

__device__ __forceinline__ uint32_t f2tf32(float f) {
    uint32_t u;
    asm("cvt.rna.tf32.f32 %0, %1;" : "=r"(u) : "f"(f));
    return u;
}

#define MMA_TF32(c, a, b0, b1)                                               \
    asm volatile("mma.sync.aligned.m16n8k8.row.col.f32.tf32.tf32.f32 "       \
        "{%0,%1,%2,%3}, {%4,%5,%6,%7}, {%8,%9}, {%0,%1,%2,%3};"              \
        : "+f"((c)[0]), "+f"((c)[1]), "+f"((c)[2]), "+f"((c)[3])             \
        : "r"((a)[0]), "r"((a)[1]), "r"((a)[2]), "r"((a)[3]),                \
          "r"(b0), "r"(b1))

// ---------------- weight pre-conversion: [Wself;Wneigh] -> tf32 ----------------
template <int OUT, int LSEL>
__global__ void convw_kernel(const float* __restrict__ Ws, const float* __restrict__ Wn) {
    float* dst = (LSEL == 0) ? g_wt0 : (LSEL == 1) ? g_wt1 : g_wt2;
    int i = blockIdx.x * blockDim.x + threadIdx.x;
    if (i < 256 * OUT) {
        int k = i / OUT, o = i % OUT;
        float v = (k < 128) ? Ws[k * OUT + o] : Wn[(k - 128) * OUT + o];
        dst[i] = __uint_as_float(f2tf32(v));
    }
}

// ---------------- CSR build ----------------
__global__ void zero_count_kernel() {
    int i = blockIdx.x * blockDim.x + threadIdx.x;
    if (i < N_NODES) g_count[i] = 0;
}

__global__ void hist_kernel(const int* __restrict__ dst) {
    int e = blockIdx.x * blockDim.x + threadIdx.x;
    if (e < N_EDGES) {
        unsigned d = (unsigned)dst[e];
        if (d < N_NODES) atomicAdd(&g_count[d], 1);
    }
}

// block-wide inclusive scan over 256 threads (8 warps)
__device__ __forceinline__ int block_incl_scan256(int v, int* wsum) {
    int lane = threadIdx.x & 31, w = threadIdx.x >> 5;
    int s = v;
#pragma unroll
    for (int off = 1; off < 32; off <<= 1) {
        int x = __shfl_up_sync(0xFFFFFFFFu, s, off);
        if (lane >= off) s += x;
    }
    if (lane == 31) wsum[w] = s;
    __syncthreads();
    if (w == 0) {
        int ws = (lane < 8) ? wsum[lane] : 0;
#pragma unroll
        for (int off = 1; off < 8; off <<= 1) {
            int x = __shfl_up_sync(0xFFFFFFFFu, ws, off);
            if (lane >= off) ws += x;
        }
        if (lane < 8) wsum[lane] = ws;
    }
    __syncthreads();
    return s + ((w > 0) ? wsum[w - 1] : 0);
}

__global__ void reduce_counts_kernel() {       // 196 blocks x 256
    __shared__ int wsum[8];
    int i = blockIdx.x * 256 + threadIdx.x;
    int v = (i < N_NODES) ? g_count[i] : 0;
    int incl = block_incl_scan256(v, wsum);
    if (threadIdx.x == 255) g_bsum[blockIdx.x] = incl;
}

__global__ void scan_partials_kernel() {       // 1 block x 256
    __shared__ int wsum[8];
    int t = threadIdx.x;
    int v = (t < 196) ? g_bsum[t] : 0;
    int incl = block_incl_scan256(v, wsum);
    if (t < 196) g_boff[t] = incl - v;         // exclusive block offset
}

// writes rowptr AND resets count[] to the exclusive prefix (scatter cursor)
__global__ void block_scan_kernel() {          // 196 blocks x 256
    __shared__ int wsum[8];
    int i = blockIdx.x * 256 + threadIdx.x;
    int v = (i < N_NODES) ? g_count[i] : 0;
    int incl = block_incl_scan256(v, wsum);
    if (i < N_NODES) {
        int excl = g_boff[blockIdx.x] + incl - v;
        g_rowptr[i + 1] = excl + v;
        g_count[i] = excl;                     // cursor (fused old cursor_kernel)
    }
    if (i == 0) g_rowptr[0] = 0;
}

__global__ void scatter_kernel(const int* __restrict__ src, const int* __restrict__ dst) {
    int e = blockIdx.x * blockDim.x + threadIdx.x;
    if (e < N_EDGES) {
        unsigned d = (unsigned)dst[e];
        unsigned s = (unsigned)src[e];
        if (d < N_NODES && s < N_NODES) {
            int pos = atomicAdd(&g_count[d], 1);
            if ((unsigned)pos < N_EDGES) g_esrc[pos] = (int)s;
        }
    }
}

// ---------------- mean aggregation: one warp per node ----------------
template <int HSEL>
__global__ void aggregate_kernel(const float* __restrict__ hext) {
    const float* __restrict__ h =
        (HSEL == 0) ? hext : ((HSEL == 1) ? (const float*)g_h1 : (const float*)g_h2);
    int warp = (blockIdx.x * blockDim.x + threadIdx.x) >> 5;
    int lane = threadIdx.x & 31;
    if (warp >= N_NODES) return;
    int beg = g_rowptr[warp];
    int end = g_rowptr[warp + 1];
    float ax = 0.f, ay = 0.f, az = 0.f, aw = 0.f;
    for (int i = beg; i < end; i++) {
        int s = g_esrc[i];
        float4 v = *reinterpret_cast<const float4*>(&h[(size_t)s * DIM + lane * 4]);
        ax += v.x; ay += v.y; az += v.z; aw += v.w;
    }
    float inv = (end > beg) ? (1.0f / (float)(end - beg)) : 0.0f;
    float4 r; r.x = ax * inv; r.y = ay * inv; r.z = az * inv; r.w = aw * inv;
    *reinterpret_cast<float4*>(&g_agg[(size_t)warp * DIM + lane * 4]) = r;
}

// ---------------- half-GEMM (tf32 mma): out = [act]( in @ Wt[WOFF:] [+b | +g_s] ) ----
// K = 128. Block: 256 threads (8 warps), tile 128 nodes x OUT, warp grid 4Mx2N,
// mma.sync.m16n8k8 tf32. ADD=false: +bias -> DSEL. ADD=true: +g_s, opt ReLU -> DSEL.
// HSEL: 0=ext, 1=g_h1, 2=g_h2, 3=g_agg. DSEL: 0=ext, 1=g_h1, 2=g_h2, 3=g_s.
template <int OUT, bool RELU, bool ADD, int HSEL, int DSEL, int WSEL, int WOFF>
__global__ __launch_bounds__(256)
void gemm_tc_kernel(const float* __restrict__ hinext,
                    const float* __restrict__ bias, float* __restrict__ outext) {
    const float* __restrict__ hin =
        (HSEL == 0) ? hinext :
        (HSEL == 1) ? (const float*)g_h1 :
        (HSEL == 2) ? (const float*)g_h2 : (const float*)g_agg;
    float* __restrict__ out =
        (DSEL == 0) ? outext :
        (DSEL == 1) ? (float*)g_h1 :
        (DSEL == 2) ? (float*)g_h2 : (float*)g_s;
    const float* __restrict__ Wt =
        ((WSEL == 0) ? g_wt0 : (WSEL == 1) ? g_wt1 : g_wt2) + (size_t)WOFF * OUT;

    constexpr int AP = 36;
    constexpr int BP = OUT + 8;
    constexpr int NS = OUT / 16;

    extern __shared__ float smem[];
    float* As = smem;                  // [128][AP]
    float* Bs = smem + 128 * AP;       // [32][BP]
    float* bs = Bs + 32 * BP;          // [OUT]

    const int tid   = threadIdx.x;
    const int lane  = tid & 31;
    const int wid   = tid >> 5;
    const int g     = lane >> 2;
    const int t4    = lane & 3;
    const int warpM = wid & 3;
    const int warpN = wid >> 2;
    const int node0 = blockIdx.x * 128;

    if (!ADD && tid < OUT) bs[tid] = bias[tid];

    float acc[2][NS][4];
#pragma unroll
    for (int ms = 0; ms < 2; ms++)
#pragma unroll
        for (int ns = 0; ns < NS; ns++)
#pragma unroll
            for (int c = 0; c < 4; c++) acc[ms][ns][c] = 0.f;

    for (int kt = 0; kt < 4; kt++) {
        const int k0 = kt * 32;
        // ---- stage A ----
        {
            const float4 z4 = make_float4(0.f, 0.f, 0.f, 0.f);
#pragma unroll
            for (int i = tid; i < 1024; i += 256) {
                int j  = i >> 3;
                int k4 = i & 7;
                int n  = node0 + j;
                float4 v = (n < N_NODES)
                    ? *reinterpret_cast<const float4*>(&hin[(size_t)n * DIM + k0 + k4 * 4])
                    : z4;
                float* d = &As[j * AP + k4 * 4];
                d[0] = v.x; d[1] = v.y; d[2] = v.z; d[3] = v.w;
            }
        }
        // ---- stage B (weights already tf32) ----
        {
            constexpr int N4 = 32 * OUT / 4;
#pragma unroll
            for (int i = tid; i < N4; i += 256) {
                int kk = i / (OUT / 4);
                int n4 = i % (OUT / 4);
                float4 wv = *reinterpret_cast<const float4*>(&Wt[(size_t)(k0 + kk) * OUT + n4 * 4]);
                *reinterpret_cast<float4*>(&Bs[kk * BP + n4 * 4]) = wv;
            }
        }
        __syncthreads();

#pragma unroll
        for (int ks = 0; ks < 4; ks++) {
            const int kb = ks * 8;
            uint32_t a[2][4];
#pragma unroll
            for (int ms = 0; ms < 2; ms++) {
                int r = warpM * 32 + ms * 16 + g;
                a[ms][0] = f2tf32(As[r * AP + kb + t4]);
                a[ms][1] = f2tf32(As[(r + 8) * AP + kb + t4]);
                a[ms][2] = f2tf32(As[r * AP + kb + t4 + 4]);
                a[ms][3] = f2tf32(As[(r + 8) * AP + kb + t4 + 4]);
            }
#pragma unroll
            for (int ns = 0; ns < NS; ns++) {
                int c = warpN * (OUT / 2) + ns * 8 + g;
                uint32_t b0 = __float_as_uint(Bs[(kb + t4) * BP + c]);
                uint32_t b1 = __float_as_uint(Bs[(kb + t4 + 4) * BP + c]);
                MMA_TF32(acc[0][ns], a[0], b0, b1);
                MMA_TF32(acc[1][ns], a[1], b0, b1);
            }
        }
        __syncthreads();
    }

    // ---- epilogue ----
#pragma unroll
    for (int ms = 0; ms < 2; ms++) {
#pragma unroll
        for (int ns = 0; ns < NS; ns++) {
            int col  = warpN * (OUT / 2) + ns * 8 + t4 * 2;
            int row0 = node0 + warpM * 32 + ms * 16 + g;
            int row1 = row0 + 8;
#pragma unroll
            for (int h = 0; h < 2; h++) {
                int row = (h == 0) ? row0 : row1;
                if (row < N_NODES) {
                    float2 r;
                    float c0 = acc[ms][ns][h * 2 + 0];
                    float c1 = acc[ms][ns][h * 2 + 1];
                    if (ADD) {
                        float2 s2 = *reinterpret_cast<const float2*>(
                            &g_s[(size_t)row * OUT + col]);
                        r.x = c0 + s2.x; r.y = c1 + s2.y;
                    } else {
                        r.x = c0 + bs[col]; r.y = c1 + bs[col + 1];
                    }
                    if (RELU) { r.x = fmaxf(r.x, 0.f); r.y = fmaxf(r.y, 0.f); }
                    *reinterpret_cast<float2*>(&out[(size_t)row * OUT + col]) = r;
                }
            }
        }
    }
}

// ---------------- host launcher ----------------
extern "C" void kernel_launch(void* const* d_in, const int* in_sizes, int n_in,
                              void* d_out, int out_size) {
    // size-class input identification (ordering-agnostic)
    const float* x = nullptr;
    const int*   edge[2] = {nullptr, nullptr};
    const float* w16[4]  = {nullptr, nullptr, nullptr, nullptr};
    const float* w8[2]   = {nullptr, nullptr};
    const float* b128[2] = {nullptr, nullptr};
    const float* b2 = nullptr;
    int ne = 0, n16 = 0, n8 = 0, nb = 0;
    int x_slot = -1;

    for (int i = 0; i < n_in && i < 12; i++) {
        int sz = in_sizes[i];
        if (sz == N_NODES * DIM)      { x = (const float*)d_in[i]; x_slot = i; }
        else if (sz == N_EDGES)       { if (ne < 2)  edge[ne++] = (const int*)d_in[i]; }
        else if (sz == DIM * DIM)     { if (n16 < 4) w16[n16++] = (const float*)d_in[i]; }
        else if (sz == DIM * 64)      { if (n8 < 2)  w8[n8++]   = (const float*)d_in[i]; }
        else if (sz == DIM)           { if (nb < 2)  b128[nb++] = (const float*)d_in[i]; }
        else if (sz == 64)            { b2 = (const float*)d_in[i]; }
    }

    const float *Ws0, *Wn0, *b0, *Ws1, *Wn1, *b1, *Ws2, *Wn2;
    const int *src, *dst;
    if (x_slot == 0) {
        src = edge[0]; dst = edge[1];
        Ws0 = w16[0]; Wn0 = w16[1]; Ws1 = w16[2]; Wn1 = w16[3];
        Ws2 = w8[0];  Wn2 = w8[1];
    } else {
        dst = edge[0]; src = edge[1];
        Wn0 = w16[0]; Wn1 = w16[1]; Ws0 = w16[2]; Ws1 = w16[3];
        Wn2 = w8[0];  Ws2 = w8[1];
    }
    b0 = b128[0]; b1 = b128[1];
    float* out = (float*)d_out;

    const int SMEM128 = (128 * 36 + 32 * 136 + 128) * 4;   // 36352 B
    const int SMEM64  = (128 * 36 + 32 * 72  + 64) * 4;    // 27904 B

    // streams + events (lazy, capture-legal)
    static cudaStream_t s1 = nullptr;
    static cudaEvent_t evFork, evS0, evS1, evS2, evN0, evN1;
    if (!s1) {
        cudaStreamCreateWithFlags(&s1, cudaStreamNonBlocking);
        cudaEventCreateWithFlags(&evFork, cudaEventDisableTiming);
        cudaEventCreateWithFlags(&evS0, cudaEventDisableTiming);
        cudaEventCreateWithFlags(&evS1, cudaEventDisableTiming);
        cudaEventCreateWithFlags(&evS2, cudaEventDisableTiming);
        cudaEventCreateWithFlags(&evN0, cudaEventDisableTiming);
        cudaEventCreateWithFlags(&evN1, cudaEventDisableTiming);
    }
    cudaStream_t s0 = (cudaStream_t)0;

    const int NB = (N_NODES + 255) / 256;   // 196
    const int AGG_BLOCKS  = (N_NODES * 32 + 255) / 256;
    const int GEMM_BLOCKS = (N_NODES + 127) / 128;

    cudaEventRecord(evFork, s0);
    cudaStreamWaitEvent(s1, evFork, 0);

    // ---- s1: weight conversion + self0 = x @ Ws0 + b0 -> g_s ----
    convw_kernel<128, 0><<<(256 * 128 + 255) / 256, 256, 0, s1>>>(Ws0, Wn0);
    convw_kernel<128, 1><<<(256 * 128 + 255) / 256, 256, 0, s1>>>(Ws1, Wn1);
    convw_kernel<64,  2><<<(256 * 64  + 255) / 256, 256, 0, s1>>>(Ws2, Wn2);
    gemm_tc_kernel<128, false, false, 0, 3, 0, 0><<<GEMM_BLOCKS, 256, SMEM128, s1>>>(x, b0, nullptr);
    cudaEventRecord(evS0, s1);

    // ---- s0: CSR build + agg0 (concurrent with s1) ----
    zero_count_kernel<<<NB, 256, 0, s0>>>();
    hist_kernel<<<(N_EDGES + 255) / 256, 256, 0, s0>>>(dst);
    reduce_counts_kernel<<<NB, 256, 0, s0>>>();
    scan_partials_kernel<<<1, 256, 0, s0>>>();
    block_scan_kernel<<<NB, 256, 0, s0>>>();
    scatter_kernel<<<(N_EDGES + 255) / 256, 256, 0, s0>>>(src, dst);
    aggregate_kernel<0><<<AGG_BLOCKS, 256, 0, s0>>>(x);

    // ---- join: neigh0 = relu(g_s + agg @ Wn0) -> g_h1 ----
    cudaStreamWaitEvent(s0, evS0, 0);
    gemm_tc_kernel<128, true, true, 3, 1, 0, 128><<<GEMM_BLOCKS, 256, SMEM128, s0>>>(nullptr, nullptr, nullptr);
    cudaEventRecord(evN0, s0);

    // ---- layer 1: self1 (s1) || agg1 (s0) ----
    cudaStreamWaitEvent(s1, evN0, 0);
    gemm_tc_kernel<128, false, false, 1, 3, 1, 0><<<GEMM_BLOCKS, 256, SMEM128, s1>>>(nullptr, b1, nullptr);
    cudaEventRecord(evS1, s1);
    aggregate_kernel<1><<<AGG_BLOCKS, 256, 0, s0>>>(nullptr);
    cudaStreamWaitEvent(s0, evS1, 0);
    gemm_tc_kernel<128, true, true, 3, 2, 1, 128><<<GEMM_BLOCKS, 256, SMEM128, s0>>>(nullptr, nullptr, nullptr);
    cudaEventRecord(evN1, s0);

    // ---- layer 2: self2 (s1) || agg2 (s0); final -> d_out ----
    cudaStreamWaitEvent(s1, evN1, 0);
    gemm_tc_kernel<64, false, false, 2, 3, 2, 0><<<GEMM_BLOCKS, 256, SMEM64, s1>>>(nullptr, b2, nullptr);
    cudaEventRecord(evS2, s1);
    aggregate_kernel<2><<<AGG_BLOCKS, 256, 0, s0>>>(nullptr);
    cudaStreamWaitEvent(s0, evS2, 0);
    gemm_tc_kernel<64, false, true, 3, 0, 2, 128><<<GEMM_BLOCKS, 256, SMEM64, s0>>>(nullptr, nullptr, out);
}